// round 17
// baseline (speedup 1.0000x reference)
#include <cuda_runtime.h>
#include <cuda_fp16.h>
#include <cstdint>

// Problem constants
#define BB 32
#define NN 1024
#define IN_DIM 64
#define HID 128
#define OUTD 64        // 2*LAT
#define NUM_LAYERS 3

// fp16 range management (all powers of two => exact):
#define SH_F    0.0625f           // 2^-4
#define ST2_F   0.015625f         // 2^-6
#define UNSC_F  1024.0f           // 1/(SH*ST2)
#define SP_F    6.103515625e-05f  // 2^-14
#define UNSC2_F 16384.0f          // 1/SP

// Scratch (device globals; no allocations allowed)
__device__ __half g_adjh[(size_t)BB * NN * NN];       // 67 MB fp16 adjacency
__device__ __half g_hT[2][(size_t)BB * HID * NN];     // ping-pong transposed activations (scaled SH)
__device__ __half g_xh[(size_t)BB * NN * IN_DIM];     // fp16 node features
__device__ float  g_rowsum[BB * NN];                  // per-node adjacency row sums
__device__ __half g_WlTh[NUM_LAYERS * HID * HID];     // Wl transposed, fp16
__device__ __half g_WembTh[HID * IN_DIM];             // Wemb transposed, fp16
__device__ __half g_WprojTh[2 * OUTD * 64];           // WprojT in 2 k-chunks, fp16
__device__ int    g_tick[4];                          // per-layer tile tickets

// ============================================================================
// Helpers
// ============================================================================
__device__ __forceinline__ uint32_t smem_u32(const void* p) {
    uint32_t a;
    asm("{ .reg .u64 t; cvta.to.shared.u64 t, %1; cvt.u32.u64 %0, t; }"
        : "=r"(a) : "l"(p));
    return a;
}

__device__ __forceinline__ uint32_t pack_h2(float a, float b) {
    __half2 h = __floats2half2_rn(a, b);
    return *reinterpret_cast<uint32_t*>(&h);
}

__device__ __forceinline__ void mma_f16(float c[4],
                                        uint32_t a0, uint32_t a1, uint32_t a2, uint32_t a3,
                                        uint32_t b0, uint32_t b1) {
    asm volatile(
        "mma.sync.aligned.m16n8k16.row.col.f32.f16.f16.f32 "
        "{%0,%1,%2,%3}, {%4,%5,%6,%7}, {%8,%9}, {%0,%1,%2,%3};"
        : "+f"(c[0]), "+f"(c[1]), "+f"(c[2]), "+f"(c[3])
        : "r"(a0), "r"(a1), "r"(a2), "r"(a3), "r"(b0), "r"(b1));
}

#define LDMX4(r0, r1, r2, r3, addr) \
    asm volatile("ldmatrix.sync.aligned.m8n8.x4.shared.b16 {%0,%1,%2,%3}, [%4];" \
                 : "=r"(r0), "=r"(r1), "=r"(r2), "=r"(r3) : "r"(addr))

#define CP_ASYNC16(dst, src) \
    asm volatile("cp.async.cg.shared.global [%0], [%1], 16;" :: "r"(dst), "l"(src))
#define CP_COMMIT() asm volatile("cp.async.commit_group;" ::: "memory")
#define CP_WAIT1()  asm volatile("cp.async.wait_group 1;" ::: "memory")
#define CP_WAIT0()  asm volatile("cp.async.wait_group 0;" ::: "memory")

// 16KB fp16 tile (128 rows x 64 halves, 128B rows), word-swizzled q^(r&7).
__device__ __forceinline__ void load_tile16(
    uint32_t dst, const __half* __restrict__ src, int rowstride_h, int tid)
{
#pragma unroll
    for (int i = 0; i < 4; i++) {
        int idx = tid + i * 256;
        int row = idx >> 3;
        int q   = idx & 7;
        CP_ASYNC16(dst + row * 128 + ((q ^ (row & 7)) << 4),
                   src + (size_t)row * rowstride_h + q * 8);
    }
}

// 8KB variant (64 rows x 64 halves)
__device__ __forceinline__ void load_tile8(
    uint32_t dst, const __half* __restrict__ src, int rowstride_h, int tid)
{
#pragma unroll
    for (int i = 0; i < 2; i++) {
        int idx = tid + i * 256;
        int row = idx >> 3;
        int q   = idx & 7;
        CP_ASYNC16(dst + row * 128 + ((q ^ (row & 7)) << 4),
                   src + (size_t)row * rowstride_h + q * 8);
    }
}

// ============================================================================
// Prep: weights transpose+fp16, x fp32->fp16, ticket reset
// ============================================================================
#define CONVX_BLOCKS ((BB * NN * IN_DIM) / (4 * 256))   // 2048

__global__ __launch_bounds__(256) void prep_all(
    const float* __restrict__ Wl, const float* __restrict__ Wemb,
    const float* __restrict__ Wproj, const float* __restrict__ x,
    __half* __restrict__ wlt, __half* __restrict__ wembT,
    __half* __restrict__ wpT, __half* __restrict__ xh)
{
    int bid = blockIdx.x;
    if (bid < NUM_LAYERS) {
        if (bid == 0 && threadIdx.x < 4) g_tick[threadIdx.x] = 0;   // reset tickets each replay
        const float* W = Wl + (size_t)bid * HID * HID;
        __half* T = wlt + (size_t)bid * HID * HID;
        for (int i = threadIdx.x; i < HID * HID; i += blockDim.x) {
            int n2 = i >> 7, n = i & 127;
            T[i] = __float2half(W[n * HID + n2]);
        }
    } else if (bid == NUM_LAYERS) {
        for (int i = threadIdx.x; i < HID * IN_DIM; i += blockDim.x) {
            int o = i >> 6, i2 = i & 63;
            wembT[i] = __float2half(Wemb[i2 * HID + o]);
        }
    } else if (bid == NUM_LAYERS + 1) {
        for (int i = threadIdx.x; i < 2 * OUTD * 64; i += blockDim.x) {
            int c = i >> 12, o = (i >> 6) & 63, f = i & 63;
            wpT[i] = __float2half(Wproj[(64 * c + f) * OUTD + o]);
        }
    } else {
        int idx = (bid - (NUM_LAYERS + 2)) * 256 + threadIdx.x;
        float4 v = *reinterpret_cast<const float4*>(x + (size_t)idx * 4);
        union { __half2 h[2]; uint2 u; } pk;
        pk.h[0] = __floats2half2_rn(v.x, v.y);
        pk.h[1] = __floats2half2_rn(v.z, v.w);
        *reinterpret_cast<uint2*>(xh + (size_t)idx * 4) = pk.u;
    }
}

// adj fp32 -> fp16 copy + per-row sums. One warp per adjacency row.
__global__ __launch_bounds__(256) void conv_rowsum(
    const float* __restrict__ adj, __half* __restrict__ adjh, float* __restrict__ rs)
{
    int warp = (blockIdx.x * blockDim.x + threadIdx.x) >> 5;
    int lane = threadIdx.x & 31;
    const float* src = adj + (size_t)warp * NN;
    __half* dst = adjh + (size_t)warp * NN;
    float s = 0.f;
#pragma unroll
    for (int i = 0; i < 8; i++) {
        float4 v = __ldcs(reinterpret_cast<const float4*>(src + i * 128 + lane * 4));
        s += v.x + v.y + v.z + v.w;
        union { __half2 h[2]; uint2 u; } pk;
        pk.h[0] = __floats2half2_rn(v.x, v.y);
        pk.h[1] = __floats2half2_rn(v.z, v.w);
        *reinterpret_cast<uint2*>(dst + i * 128 + lane * 4) = pk.u;
    }
#pragma unroll
    for (int off = 16; off; off >>= 1) s += __shfl_xor_sync(0xFFFFFFFFu, s, off);
    if (lane == 0) rs[warp] = s;
}

// ============================================================================
// Embed: hT0 = (x @ Wemb)^T * SH  (unchanged BM=128 kernel)
// ============================================================================
#define ETILE 16384
#define EHBUF_STRIDE 136
#define EHBUF_OFF (2 * ETILE)
#define SMTOT_E (EHBUF_OFF + 128 * EHBUF_STRIDE * 2)    // 67584

__global__ __launch_bounds__(256, 2) void embed_mma(
    const __half* __restrict__ xh, const __half* __restrict__ wembT,
    __half* __restrict__ hTout)
{
    extern __shared__ __align__(1024) char smem[];
    const uint32_t sb = smem_u32(smem);
    const int tid = threadIdx.x;
    const int lid = tid & 31;
    const int wid = tid >> 5;
    const int row0 = blockIdx.x * 128;
    const int b = row0 >> 10;
    const int node0 = row0 & (NN - 1);

    const int g = lid >> 2, tg = lid & 3;
    const int m_warp = (wid & 1) * 64;
    const int n_warp = (wid >> 1) * 32;
    const int xr = lid & 7;
    const int rAo = ((lid >> 3) & 1) * 8;
    const int w0A = (lid >> 4) & 1;
    uint32_t Qa[4];
#pragma unroll
    for (int mt = 0; mt < 4; mt++) {
        int r = m_warp + mt * 16 + rAo + xr;
        Qa[mt] = (uint32_t)(r * 128 + ((w0A ^ xr) << 4));
    }
    const int w0B = (lid >> 3) & 1;
    const int ntB = (lid >> 4) & 1;
    uint32_t Qb[2];
#pragma unroll
    for (int p = 0; p < 2; p++) {
        int rn = n_warp + (p * 2 + ntB) * 8 + xr;
        Qb[p] = (uint32_t)(rn * 128 + ((w0B ^ xr) << 4));
    }

    load_tile16(sb,         xh + (size_t)row0 * IN_DIM, IN_DIM, tid);
    load_tile16(sb + ETILE, wembT, IN_DIM, tid);
    CP_COMMIT();

    float acc[4][4][4];
#pragma unroll
    for (int mt = 0; mt < 4; mt++)
#pragma unroll
        for (int nt = 0; nt < 4; nt++)
#pragma unroll
            for (int r = 0; r < 4; r++) acc[mt][nt][r] = 0.f;

    CP_WAIT0();
    __syncthreads();

#pragma unroll
    for (int kk = 0; kk < 4; kk++) {
        const uint32_t kx = (uint32_t)kk << 5;
        uint32_t bf[4][2];
        LDMX4(bf[0][0], bf[0][1], bf[1][0], bf[1][1], (sb + ETILE + Qb[0]) ^ kx);
        LDMX4(bf[2][0], bf[2][1], bf[3][0], bf[3][1], (sb + ETILE + Qb[1]) ^ kx);
#pragma unroll
        for (int mt = 0; mt < 4; mt++) {
            uint32_t a0, a1, a2, a3;
            LDMX4(a0, a1, a2, a3, (sb + Qa[mt]) ^ kx);
#pragma unroll
            for (int nt = 0; nt < 4; nt++)
                mma_f16(acc[mt][nt], a0, a1, a2, a3, bf[nt][0], bf[nt][1]);
        }
    }

    __half* hb = reinterpret_cast<__half*>(smem + EHBUF_OFF);
#pragma unroll
    for (int mt = 0; mt < 4; mt++) {
        int mr = m_warp + mt * 16 + g;
#pragma unroll
        for (int nt = 0; nt < 4; nt++) {
            int col = n_warp + nt * 8 + 2 * tg;
            hb[(col)     * EHBUF_STRIDE + mr]     = __float2half(acc[mt][nt][0] * SH_F);
            hb[(col + 1) * EHBUF_STRIDE + mr]     = __float2half(acc[mt][nt][1] * SH_F);
            hb[(col)     * EHBUF_STRIDE + mr + 8] = __float2half(acc[mt][nt][2] * SH_F);
            hb[(col + 1) * EHBUF_STRIDE + mr + 8] = __float2half(acc[mt][nt][3] * SH_F);
        }
    }
    __syncthreads();
#pragma unroll
    for (int p = 0; p < 8; p++) {
        int idx = tid + p * 256;
        int c = idx >> 4, u = idx & 15;
        uint4 v = *reinterpret_cast<const uint4*>(hb + c * EHBUF_STRIDE + u * 8);
        *reinterpret_cast<uint4*>(
            hTout + ((size_t)(b * HID + c)) * NN + node0 + u * 8) = v;
    }
}

// ============================================================================
// Persistent ticketed GCN layer, BM=64 tiles (512 tiles, grid 296):
//   acc = adjh[64 rows] @ (h*SH)^T ; Tbuf = acc/64 ; h' = relu(1024*(Tbuf@Wl)+rs*bl)
//   LAST=false: store (h'*SH)^T fp16
//   LAST=true : Tbuf2 = h'*2^-14 ; out = (16384*(Tbuf2@Wproj)+bproj)*mask
// smem: A-slots 3x8KB @0 | B-slots 3x16KB @24576 | hbuf 18432 @73728 | tick @92160
// Tbuf -> A-slots 0,1 ; WlT -> B-slots 1,2 ; WprojT -> B-slot 0 (2x8KB).
// ============================================================================
#define BKH 64
#define NITH (NN / BKH)           // 16
#define ABOFF 24576
#define HB_OFF 73728
#define HB_STRIDE 72
#define TICK_OFF 92160
#define SMTOT64 92672
#define NTILES (BB * (NN / 64))   // 512
#define PGRID 296

template<bool LAST>
__global__ __launch_bounds__(256, 2) void adj_layer(
    int* __restrict__ tick,
    const __half* __restrict__ adjh, const __half* __restrict__ hTin,
    const __half* __restrict__ wlt,  const float* __restrict__ bl,
    const float* __restrict__ rowsum, __half* __restrict__ hTout,
    const __half* __restrict__ wpT, const float* __restrict__ bproj,
    const float* __restrict__ mask, float* __restrict__ out)
{
    extern __shared__ __align__(1024) char smem[];
    const uint32_t sb = smem_u32(smem);
    const int tid = threadIdx.x;
    const int lid = tid & 31;
    const int wid = tid >> 5;

    const int g  = lid >> 2, tg = lid & 3;
    const int n_warp = wid * 16;
    const int xr  = lid & 7;
    const int rAo = ((lid >> 3) & 1) * 8;
    const int w0A = (lid >> 4) & 1;
    uint32_t Qa[4];
#pragma unroll
    for (int mt = 0; mt < 4; mt++) {
        int r = mt * 16 + rAo + xr;                 // rows 0..63
        Qa[mt] = (uint32_t)(r * 128 + ((w0A ^ xr) << 4));
    }
    const int w0B = (lid >> 3) & 1;
    const int ntB = (lid >> 4) & 1;
    const uint32_t Qb = (uint32_t)((n_warp + ntB * 8 + xr) * 128 + ((w0B ^ xr) << 4));

    int* tickS = reinterpret_cast<int*>(smem + TICK_OFF);

    for (;;) {
        if (tid == 0) *tickS = atomicAdd(tick, 1);
        __syncthreads();
        const int tile = *tickS;
        if (tile >= NTILES) return;

        const int b    = tile >> 4;
        const int row0 = (tile & 15) * 64;
        const __half* Ab = adjh + (size_t)b * NN * NN + (size_t)row0 * NN;
        const __half* Bb = hTin + (size_t)b * HID * NN;

        float acc[4][2][4];
#pragma unroll
        for (int mt = 0; mt < 4; mt++)
#pragma unroll
            for (int nt = 0; nt < 2; nt++)
#pragma unroll
                for (int r = 0; r < 4; r++) acc[mt][nt][r] = 0.f;

        // ---- mainloop ----
#pragma unroll
        for (int p = 0; p < 2; p++) {
            load_tile8 (sb + p * 8192,          Ab + p * BKH, NN, tid);
            load_tile16(sb + ABOFF + p * 16384, Bb + p * BKH, NN, tid);
            CP_COMMIT();
        }

        for (int it = 0; it < NITH; it++) {
            const int s = it % 3;
            CP_WAIT1();
            __syncthreads();

            const uint32_t sA = sb + s * 8192;
            const uint32_t sB = sb + ABOFF + s * 16384;

            uint32_t bf[2][2][2];
            uint32_t af[2][4];
            LDMX4(bf[0][0][0], bf[0][0][1], bf[0][1][0], bf[0][1][1], sB + Qb);
            LDMX4(af[0][0], af[0][1], af[0][2], af[0][3], sA + Qa[0]);

#pragma unroll
            for (int kk = 0; kk < 4; kk++) {
                const uint32_t kx  = (uint32_t)kk << 5;
                const uint32_t kxn = (uint32_t)(kk + 1) << 5;
                const int cb = kk & 1, nb = cb ^ 1;
                if (kk < 3)
                    LDMX4(bf[nb][0][0], bf[nb][0][1], bf[nb][1][0], bf[nb][1][1],
                          (sB + Qb) ^ kxn);
#pragma unroll
                for (int mt = 0; mt < 4; mt++) {
                    const int ca = mt & 1, na = ca ^ 1;
                    if (mt < 3) {
                        LDMX4(af[na][0], af[na][1], af[na][2], af[na][3],
                              (sA + Qa[mt + 1]) ^ kx);
                    } else if (kk < 3) {
                        LDMX4(af[na][0], af[na][1], af[na][2], af[na][3],
                              (sA + Qa[0]) ^ kxn);
                    }
#pragma unroll
                    for (int nt = 0; nt < 2; nt++)
                        mma_f16(acc[mt][nt], af[ca][0], af[ca][1], af[ca][2], af[ca][3],
                                bf[cb][nt][0], bf[cb][nt][1]);
                }
                if (kk == 0) {
                    if (it + 2 < NITH) {
                        const int sl = (it + 2) % 3;
                        load_tile8 (sb + sl * 8192,          Ab + (it + 2) * BKH, NN, tid);
                        load_tile16(sb + ABOFF + sl * 16384, Bb + (it + 2) * BKH, NN, tid);
                    }
                    CP_COMMIT();
                }
            }
        }

        // ---- epilogue 1: h' = relu(1024*(Tbuf @ Wl) + rowsum*bl) ----
        load_tile16(sb + ABOFF + 16384, wlt, HID, tid);     // WlT ch0 -> B-slot 1 (idle since it=13)
        CP_COMMIT();
        __syncthreads();                                    // it=15 MMAs done (A0/B0 free)
        load_tile16(sb + ABOFF + 32768, wlt + 64, HID, tid);// WlT ch1 -> B-slot 2
        if (LAST) {
            load_tile8(sb + ABOFF,        wpT,             64, tid);   // WprojT ch0 -> B-slot0
            load_tile8(sb + ABOFF + 8192, wpT + OUTD * 64, 64, tid);   // ch1 -> B-slot0+8K
        }
        CP_COMMIT();

        // Tbuf = acc * ST2 into A-slots 0 (cols 0-63, warps 0-3) / 1 (64-127, warps 4-7)
        {
            char* tb = smem + (wid >> 2) * 8192;
            const int lpb = (wid & 3) * 8;
#pragma unroll
            for (int mt = 0; mt < 4; mt++) {
                int mr = mt * 16 + g;
#pragma unroll
                for (int nt = 0; nt < 2; nt++) {
                    int lp = lpb + nt * 4 + tg;
                    int w = lp >> 2, inner = (lp & 3) * 4;
                    *reinterpret_cast<uint32_t*>(
                        tb + mr * 128 + ((w ^ (mr & 7)) << 4) + inner) =
                        pack_h2(acc[mt][nt][0] * ST2_F, acc[mt][nt][1] * ST2_F);
                    *reinterpret_cast<uint32_t*>(
                        tb + (mr + 8) * 128 + ((w ^ ((mr + 8) & 7)) << 4) + inner) =
                        pack_h2(acc[mt][nt][2] * ST2_F, acc[mt][nt][3] * ST2_F);
                }
            }
        }
        CP_WAIT0();
        __syncthreads();

        float acc2[4][2][4];
#pragma unroll
        for (int mt = 0; mt < 4; mt++)
#pragma unroll
            for (int nt = 0; nt < 2; nt++)
#pragma unroll
                for (int r = 0; r < 4; r++) acc2[mt][nt][r] = 0.f;

#pragma unroll
        for (int ch = 0; ch < 2; ch++) {
            const uint32_t sT = sb + ch * 8192;                   // Tbuf
            const uint32_t sW = sb + ABOFF + (1 + ch) * 16384;    // WlT
#pragma unroll
            for (int kk = 0; kk < 4; kk++) {
                const uint32_t kx = (uint32_t)kk << 5;
                uint32_t bf2[2][2];
                LDMX4(bf2[0][0], bf2[0][1], bf2[1][0], bf2[1][1], (sW + Qb) ^ kx);
#pragma unroll
                for (int mt = 0; mt < 4; mt++) {
                    uint32_t a0, a1, a2, a3;
                    LDMX4(a0, a1, a2, a3, (sT + Qa[mt]) ^ kx);
#pragma unroll
                    for (int nt = 0; nt < 2; nt++)
                        mma_f16(acc2[mt][nt], a0, a1, a2, a3, bf2[nt][0], bf2[nt][1]);
                }
            }
        }

        const float* rsb = rowsum + b * NN + row0;
        float rlo[4], rhi[4];
#pragma unroll
        for (int mt = 0; mt < 4; mt++) {
            rlo[mt] = rsb[mt * 16 + g];
            rhi[mt] = rsb[mt * 16 + g + 8];
        }
        float b0v[2], b1v[2];
#pragma unroll
        for (int nt = 0; nt < 2; nt++) {
            int col = n_warp + nt * 8 + 2 * tg;
            b0v[nt] = bl[col];
            b1v[nt] = bl[col + 1];
        }

        __half* hb = reinterpret_cast<__half*>(smem + HB_OFF);

        if (LAST) __syncthreads();   // all epilogue-1 MMA reads of A-slots done

#pragma unroll
        for (int mt = 0; mt < 4; mt++) {
            int mr = mt * 16 + g;
#pragma unroll
            for (int nt = 0; nt < 2; nt++) {
                int col = n_warp + nt * 8 + 2 * tg;
                float v00 = fmaxf(fmaf(acc2[mt][nt][0], UNSC_F, rlo[mt] * b0v[nt]), 0.f);
                float v01 = fmaxf(fmaf(acc2[mt][nt][1], UNSC_F, rlo[mt] * b1v[nt]), 0.f);
                float v10 = fmaxf(fmaf(acc2[mt][nt][2], UNSC_F, rhi[mt] * b0v[nt]), 0.f);
                float v11 = fmaxf(fmaf(acc2[mt][nt][3], UNSC_F, rhi[mt] * b1v[nt]), 0.f);
                if (LAST) {
                    char* tb = smem + (wid >> 2) * 8192;
                    const int lpb = (wid & 3) * 8;
                    int lp = lpb + nt * 4 + tg;
                    int w = lp >> 2, inner = (lp & 3) * 4;
                    *reinterpret_cast<uint32_t*>(
                        tb + mr * 128 + ((w ^ (mr & 7)) << 4) + inner) =
                        pack_h2(v00 * SP_F, v01 * SP_F);
                    *reinterpret_cast<uint32_t*>(
                        tb + (mr + 8) * 128 + ((w ^ ((mr + 8) & 7)) << 4) + inner) =
                        pack_h2(v10 * SP_F, v11 * SP_F);
                } else {
                    hb[(col)     * HB_STRIDE + mr]     = __float2half(v00 * SH_F);
                    hb[(col + 1) * HB_STRIDE + mr]     = __float2half(v01 * SH_F);
                    hb[(col)     * HB_STRIDE + mr + 8] = __float2half(v10 * SH_F);
                    hb[(col + 1) * HB_STRIDE + mr + 8] = __float2half(v11 * SH_F);
                }
            }
        }

        if (!LAST) {
            __syncthreads();
            // h'T store: feat row c -> hTout[b][c][row0 .. row0+63]
#pragma unroll
            for (int p = 0; p < 4; p++) {
                int idx = tid + p * 256;               // 0..1023: c=idx>>3, u=idx&7
                int c = idx >> 3, u = idx & 7;
                uint4 v = *reinterpret_cast<const uint4*>(hb + c * HB_STRIDE + u * 8);
                *reinterpret_cast<uint4*>(
                    hTout + ((size_t)(b * HID + c)) * NN + row0 + u * 8) = v;
            }
        } else {
            __syncthreads();                           // Tbuf2 fully written
            if (wid < 4) {                             // warps 0-3: 64x16 out tiles
                const int n2 = wid * 16;
                const uint32_t Qb2 = (uint32_t)((n2 + ntB * 8 + xr) * 128 + ((w0B ^ xr) << 4));
                float acc3[4][2][4];
#pragma unroll
                for (int mt = 0; mt < 4; mt++)
#pragma unroll
                    for (int nt = 0; nt < 2; nt++)
#pragma unroll
                        for (int r = 0; r < 4; r++) acc3[mt][nt][r] = 0.f;
#pragma unroll
                for (int ch = 0; ch < 2; ch++) {
                    const uint32_t sT = sb + ch * 8192;
                    const uint32_t sW = sb + ABOFF + ch * 8192;     // WprojT in B-slot 0
#pragma unroll
                    for (int kk = 0; kk < 4; kk++) {
                        const uint32_t kx = (uint32_t)kk << 5;
                        uint32_t bf3[2][2];
                        LDMX4(bf3[0][0], bf3[0][1], bf3[1][0], bf3[1][1], (sW + Qb2) ^ kx);
#pragma unroll
                        for (int mt = 0; mt < 4; mt++) {
                            uint32_t a0, a1, a2, a3;
                            LDMX4(a0, a1, a2, a3, (sT + Qa[mt]) ^ kx);
#pragma unroll
                            for (int nt = 0; nt < 2; nt++)
                                mma_f16(acc3[mt][nt], a0, a1, a2, a3, bf3[nt][0], bf3[nt][1]);
                        }
                    }
                }
#pragma unroll
                for (int mt = 0; mt < 4; mt++) {
                    int grow = b * NN + row0 + mt * 16 + g;
                    float m0 = mask[grow], m1 = mask[grow + 8];
#pragma unroll
                    for (int nt = 0; nt < 2; nt++) {
                        int col = n2 + nt * 8 + 2 * tg;
                        float pb0 = bproj[col], pb1 = bproj[col + 1];
                        float2 p0, p1;
                        p0.x = fmaf(acc3[mt][nt][0], UNSC2_F, pb0) * m0;
                        p0.y = fmaf(acc3[mt][nt][1], UNSC2_F, pb1) * m0;
                        p1.x = fmaf(acc3[mt][nt][2], UNSC2_F, pb0) * m1;
                        p1.y = fmaf(acc3[mt][nt][3], UNSC2_F, pb1) * m1;
                        *reinterpret_cast<float2*>(&out[(size_t)grow * OUTD + col])       = p0;
                        *reinterpret_cast<float2*>(&out[(size_t)(grow + 8) * OUTD + col]) = p1;
                    }
                }
            }
        }
        // loop back: ticket barrier separates this tile's smem reads from next tile's loads
    }
}

// ============================================================================
// Launch — fork-join DAG + persistent ticketed layers.
// Inputs: 0 node_features [B,N,64] | 1 adjacency [B,N,N] | 2 node_mask [B,N,1]
//         3 W_embed [64,128] | 4 Wl [3,128,128] | 5 bl [3,128]
//         6 W_proj [128,64]  | 7 b_proj [64]      Output: [B,N,64] f32
// ============================================================================
extern "C" void kernel_launch(void* const* d_in, const int* in_sizes, int n_in,
                              void* d_out, int out_size)
{
    const float* x     = (const float*)d_in[0];
    const float* adj   = (const float*)d_in[1];
    const float* mask  = (const float*)d_in[2];
    const float* Wemb  = (const float*)d_in[3];
    const float* Wl    = (const float*)d_in[4];
    const float* bl    = (const float*)d_in[5];
    const float* Wproj = (const float*)d_in[6];
    const float* bproj = (const float*)d_in[7];
    float* out = (float*)d_out;

    __half *adjh = nullptr, *hT = nullptr, *wlt = nullptr;
    __half *xh = nullptr, *wembT = nullptr, *wpT = nullptr;
    float *rs = nullptr;
    int *tick = nullptr;
    cudaGetSymbolAddress((void**)&adjh,  g_adjh);
    cudaGetSymbolAddress((void**)&hT,    g_hT);
    cudaGetSymbolAddress((void**)&wlt,   g_WlTh);
    cudaGetSymbolAddress((void**)&xh,    g_xh);
    cudaGetSymbolAddress((void**)&wembT, g_WembTh);
    cudaGetSymbolAddress((void**)&wpT,   g_WprojTh);
    cudaGetSymbolAddress((void**)&rs,    g_rowsum);
    cudaGetSymbolAddress((void**)&tick,  g_tick);
    __half* hT0 = hT;
    __half* hT1 = hT + (size_t)BB * HID * NN;

    cudaFuncSetAttribute(adj_layer<false>,
                         cudaFuncAttributeMaxDynamicSharedMemorySize, SMTOT64);
    cudaFuncSetAttribute(adj_layer<true>,
                         cudaFuncAttributeMaxDynamicSharedMemorySize, SMTOT64);
    cudaFuncSetAttribute(embed_mma,
                         cudaFuncAttributeMaxDynamicSharedMemorySize, SMTOT_E);

    // Fork: conv_rowsum on side stream, prep+embed on main stream.
    cudaStream_t s2;
    cudaEvent_t evFork, evJoin;
    cudaStreamCreateWithFlags(&s2, cudaStreamNonBlocking);
    cudaEventCreateWithFlags(&evFork, cudaEventDisableTiming);
    cudaEventCreateWithFlags(&evJoin, cudaEventDisableTiming);

    cudaEventRecord(evFork, 0);
    cudaStreamWaitEvent(s2, evFork, 0);
    conv_rowsum<<<BB * NN / 8, 256, 0, s2>>>(adj, adjh, rs);
    cudaEventRecord(evJoin, s2);

    prep_all<<<NUM_LAYERS + 2 + CONVX_BLOCKS, 256>>>(
        Wl, Wemb, Wproj, x, wlt, wembT, wpT, xh);
    embed_mma<<<BB * NN / 128, 256, SMTOT_E>>>(xh, wembT, hT0);

    cudaStreamWaitEvent(0, evJoin, 0);   // join before layer 1

    adj_layer<false><<<PGRID, 256, SMTOT64>>>(
        tick + 0, adjh, hT0, wlt,                 bl,           rs, hT1,
        nullptr, nullptr, nullptr, nullptr);
    adj_layer<false><<<PGRID, 256, SMTOT64>>>(
        tick + 1, adjh, hT1, wlt + HID * HID,     bl + HID,     rs, hT0,
        nullptr, nullptr, nullptr, nullptr);
    adj_layer<true><<<PGRID, 256, SMTOT64>>>(
        tick + 2, adjh, hT0, wlt + 2 * HID * HID, bl + 2 * HID, rs, nullptr,
        wpT, bproj, mask, out);

    cudaEventDestroy(evFork);
    cudaEventDestroy(evJoin);
    cudaStreamDestroy(s2);
}